// round 8
// baseline (speedup 1.0000x reference)
#include <cuda_runtime.h>
#include <cuda_fp16.h>
#include <math.h>

#define NB   4
#define CC   256
#define HH   128
#define WW   128
#define NPIX (HH*WW)            // 16384
#define NPIX_TOT (NB*NPIX)      // 65536
#define NPTS 5
#define G    2                  // channels per CTA, packed half2 in smem (64 KB)
#define CG   (CC / G)           // 128 channel-groups per batch
#define SCALE 0.125f
#define TPB  512

static __device__ __forceinline__ unsigned pack_h2(float a, float b) {
    half2 h = __floats2half2_rn(a, b);
    return *reinterpret_cast<unsigned*>(&h);
}
static __device__ __forceinline__ float2 unpack_h2(unsigned u) {
    half2 h = *reinterpret_cast<half2*>(&u);
    return __half22float2(h);
}

// Packed per-(n,h,w,point) table: x = y_low*W+x_low (or -1 invalid), y = half2(lx, ly)
__device__ int2 g_tab[NPTS][NPIX_TOT];

__global__ void FR_precompute_kernel(const float* __restrict__ bb) {
    int i = blockIdx.x * blockDim.x + threadIdx.x;
    if (i >= NPIX_TOT) return;
    const float* b = bb + (size_t)i * 5;
    float cx = b[0], cy = b[1], w = b[2], h = b[3], t = b[4];
    float st, ct;
    sincosf(t, &st, &ct);
    float vx =  w * ct * 0.5f, vy = w * st * 0.5f;
    float wx = -h * st * 0.5f, wy = h * ct * 0.5f;

    float pxs[NPTS] = {cx, cx + vx + wx, cx - vx + wx, cx - vx - wx, cx + vx - wx};
    float pys[NPTS] = {cy, cy + vy + wy, cy - vy + wy, cy - vy - wy, cy + vy - wy};

#pragma unroll
    for (int p = 0; p < NPTS; p++) {
        float x = pxs[p] * SCALE;
        float y = pys[p] * SCALE;
        bool valid = (y >= -1.0f) && (y <= (float)HH) && (x >= -1.0f) && (x <= (float)WW);
        y = fmaxf(y, 0.0f);
        x = fmaxf(x, 0.0f);
        int yl = min((int)floorf(y), HH - 1);
        int xl = min((int)floorf(x), WW - 1);
        if (yl >= HH - 1) y = (float)yl;   // mmcv border rule
        if (xl >= WW - 1) x = (float)xl;
        float ly = y - (float)yl;
        float lx = x - (float)xl;
        int off = yl * WW + xl;
        int2 e;
        e.x = valid ? off : -1;
        e.y = (int)pack_h2(lx, ly);
        g_tab[p][i] = e;
    }
}

// Decode one table entry and accumulate its 4 corner gathers (2 channels) into a0,a1.
static __device__ __forceinline__ void point_acc2(const unsigned* __restrict__ sq, int2 t,
                                                  float& a0, float& a1) {
    float vf = (t.x >= 0) ? 1.0f : 0.0f;
    int off = max(t.x, 0);
    float2 l = unpack_h2((unsigned)t.y);
    float lx = l.x, ly = l.y;
    int xl = off & (WW - 1);
    int yl = off >> 7;
    int dx  = (xl < WW - 1) ? 1  : 0;
    int dyw = (yl < HH - 1) ? WW : 0;
    float hx = 1.0f - lx, hy = 1.0f - ly;
    float w00 = vf * hy * hx;
    float w01 = vf * hy * lx;
    float w10 = vf * ly * hx;
    float w11 = vf * ly * lx;

    unsigned v0 = sq[off];
    unsigned v1 = sq[off + dx];
    unsigned v2 = sq[off + dyw];
    unsigned v3 = sq[off + dyw + dx];

    float2 c;
    c = unpack_h2(v0); a0 += w00 * c.x; a1 += w00 * c.y;
    c = unpack_h2(v1); a0 += w01 * c.x; a1 += w01 * c.y;
    c = unpack_h2(v2); a0 += w10 * c.x; a1 += w10 * c.y;
    c = unpack_h2(v3); a0 += w11 * c.x; a1 += w11 * c.y;
}

// One CTA per (batch, pair of channels). 64 KB smem/CTA -> 3 CTAs/SM (48 warps):
// occupancy does the latency hiding; body stays simple/sequential to fit 42 regs.
__global__ __launch_bounds__(TPB, 3)
void FR_refine_kernel(const float* __restrict__ feat, float* __restrict__ out) {
    extern __shared__ unsigned int sq[];   // [NPIX] x packed half2 (2 channels)

    int bx = blockIdx.x;
    int n  = bx / CG;
    int c0 = (bx % CG) * G;
    const float* f0 = feat + ((size_t)n * CC + c0) * NPIX;

    // Vectorized fill: 2 planes -> packed half2 per pixel.
    {
        const float4* s0 = (const float4*)f0;
        const float4* s1 = (const float4*)(f0 + NPIX);
        uint4* d = (uint4*)sq;
        for (int q = threadIdx.x; q < NPIX/4; q += TPB) {
            float4 a = s0[q], b = s1[q];
            uint4 pk;
            pk.x = pack_h2(a.x, b.x);
            pk.y = pack_h2(a.y, b.y);
            pk.z = pack_h2(a.z, b.z);
            pk.w = pack_h2(a.w, b.w);
            d[q] = pk;
        }
    }
    __syncthreads();

    int tbase = n * NPIX;
    float* ob = out + ((size_t)n * CC + c0) * NPIX;

    for (int pix = threadIdx.x; pix < NPIX; pix += TPB) {
        // residual in fp32 straight from gmem (L2-resident), consumed at the end
        float r0 = f0[pix];
        float r1 = f0[pix + NPIX];

        int2 e0 = g_tab[0][tbase + pix];
        int2 e1 = g_tab[1][tbase + pix];
        int2 e2 = g_tab[2][tbase + pix];
        int2 e3 = g_tab[3][tbase + pix];
        int2 e4 = g_tab[4][tbase + pix];

        float a0 = 0.f, a1 = 0.f;
        point_acc2(sq, e0, a0, a1);
        point_acc2(sq, e1, a0, a1);
        point_acc2(sq, e2, a0, a1);
        point_acc2(sq, e3, a0, a1);
        point_acc2(sq, e4, a0, a1);

        ob[pix]        = a0 + r0;
        ob[pix + NPIX] = a1 + r1;
    }
}

extern "C" void kernel_launch(void* const* d_in, const int* in_sizes, int n_in,
                              void* d_out, int out_size) {
    const float* feat = (const float*)d_in[0];  // [4,256,128,128] f32
    const float* bb   = (const float*)d_in[1];  // [4,128,128,5]   f32
    float*       out  = (float*)d_out;          // [4,256,128,128] f32

    FR_precompute_kernel<<<(NPIX_TOT + 255) / 256, 256>>>(bb);

    size_t smem = (size_t)NPIX * 4;   // 65536 B
    cudaFuncSetAttribute(FR_refine_kernel,
                         cudaFuncAttributeMaxDynamicSharedMemorySize, (int)smem);
    FR_refine_kernel<<<NB * CG, TPB, smem>>>(feat, out);
}